// round 3
// baseline (speedup 1.0000x reference)
#include <cuda_runtime.h>
#include <cstdint>

// Problem constants
#define BATCH 16
#define NA    3
#define NC    20
#define NATTR 25          // 5 + NC
#define IH    52
#define IW    52
#define HW    2704        // IH*IW
#define NBOX  8112        // NA*HW
#define NPAD  8192
#define TOPK  2048
#define STRIDE_F 8.0f

// Accurate libdevice expf (XLA's f32 exp lowering), immune to --use_fast_math.
extern "C" __device__ float __nv_expf(float);

// Scratch (allocation-free: __device__ globals)
__device__ float g_conf[BATCH][NBOX];
__device__ int   g_cls [BATCH][NBOX];
__device__ int   g_top [BATCH][TOPK];

// ---------------------------------------------------------------------------
// Bitwise replica of XLA:GPU's tanh (llvm_ir::EmitFastTanh): Eigen ptanh
// rational approximation, fma-contracted Horner (NVPTX AllowFPOpFusion=Fast),
// rn division, |x| < 4e-4 -> x fast path, clamp to +-7.90531110763549805.
// ---------------------------------------------------------------------------
__device__ __forceinline__ float xla_tanhf(float x) {
    float ax = fabsf(x);
    float xc = fminf(fmaxf(x, -7.90531110763549805f), 7.90531110763549805f);
    float x2 = __fmul_rn(xc, xc);
    float p = -2.76076847742355e-16f;
    p = __fmaf_rn(x2, p, 2.00018790482477e-13f);
    p = __fmaf_rn(x2, p, -8.60467152213735e-11f);
    p = __fmaf_rn(x2, p, 5.12229709037114e-08f);
    p = __fmaf_rn(x2, p, 1.48572235717979e-05f);
    p = __fmaf_rn(x2, p, 6.37261928875436e-04f);
    p = __fmaf_rn(x2, p, 4.89352455891786e-03f);
    p = __fmul_rn(xc, p);
    float q = 1.19825839466702e-06f;
    q = __fmaf_rn(x2, q, 1.18534705686654e-04f);
    q = __fmaf_rn(x2, q, 2.26843463243900e-03f);
    q = __fmaf_rn(x2, q, 4.89352518554385e-03f);
    float r = __fdiv_rn(p, q);
    return (ax < 0.0004f) ? x : r;
}

// XLA logistic expansion: 0.5 + 0.5 * tanh(0.5 * x).  0.5*t is exact, so the
// final fma equals the expander's add+mul bitwise.
__device__ __forceinline__ float sigmoid_xla(float x) {
    float t = xla_tanhf(__fmul_rn(0.5f, x));
    return __fmaf_rn(0.5f, t, 0.5f);
}

// ---------------------------------------------------------------------------
// Kernel 1: decode. 128 threads/block, one thread per box; SMEM-staged
// transpose so the 25-attr rows are written coalesced.
// in:  [B, NA*NATTR, IH, IW]  (attr stride = HW)
// out: [B, NBOX, NATTR] = (bx, by, bw, bh, conf, cls0..cls19)
// ---------------------------------------------------------------------------
__global__ void decode_kernel(const float* __restrict__ in,
                              const float* __restrict__ anchors,
                              float* __restrict__ out) {
    __shared__ float s_out[128 * NATTR];

    int t = blockIdx.x * 128 + threadIdx.x;     // grid sized exactly: no tail
    int b = t / NBOX, n = t % NBOX;
    int a = n / HW,   r = n % HW;
    int gy = r / IW,  gx = r % IW;

    const float* base = in + ((size_t)(b * NA + a) * NATTR) * HW + r;
    float t0 = base[0 * HW];
    float t1 = base[1 * HW];
    float t2 = base[2 * HW];
    float t3 = base[3 * HW];
    float t4 = base[4 * HW];

    // scaled anchor = anchor / 8 (rn div), then *8 at the end — reference order.
    float aw = __fdiv_rn(anchors[a * 2 + 0], STRIDE_F);
    float ah = __fdiv_rn(anchors[a * 2 + 1], STRIDE_F);

    float sx = sigmoid_xla(t0);
    float sy = sigmoid_xla(t1);
    float bx = __fmul_rn(__fadd_rn(sx, (float)gx), STRIDE_F);
    float by = __fmul_rn(__fadd_rn(sy, (float)gy), STRIDE_F);
    float bw = __fmul_rn(__fmul_rn(__nv_expf(t2), aw), STRIDE_F);
    float bh = __fmul_rn(__fmul_rn(__nv_expf(t3), ah), STRIDE_F);
    float conf = sigmoid_xla(t4);

    float* so = s_out + threadIdx.x * NATTR;
    so[0] = bx; so[1] = by; so[2] = bw; so[3] = bh; so[4] = conf;

    // class sigmoids + argmax over the SIGMOID values (first-max wins),
    // matching jnp.argmax(sigmoid(logits)).
    float bestv = -3.402823466e+38f;
    int best = 0;
#pragma unroll
    for (int c = 0; c < NC; c++) {
        float v = sigmoid_xla(base[(5 + c) * HW]);
        so[5 + c] = v;
        if (v > bestv) { bestv = v; best = c; }
    }
    g_conf[b][n] = conf;
    g_cls[b][n]  = best;
    __syncthreads();

    // coalesced flush of this block's 128*25 contiguous floats
    float* oblk = out + (size_t)(blockIdx.x) * 128 * NATTR;
    for (int k = threadIdx.x; k < 128 * NATTR; k += 128)
        oblk[k] = s_out[k];
}

// ---------------------------------------------------------------------------
// Kernel 2: per-batch top-K via bitonic sort of packed 64-bit keys.
// key = (conf_bits << 32) | (0xFFFFFFFF - idx); conf > 0 so float bits are
// order-monotone. Descending sort => conf desc, then index asc (matches
// stable top_k tie-break). Pad entries key = 0.
// ---------------------------------------------------------------------------
extern __shared__ unsigned long long s_keys[];

__global__ void sort_kernel(float* __restrict__ out_topidx) {
    int b   = blockIdx.x;
    int tid = threadIdx.x;
    int nthr = blockDim.x;

    for (int i = tid; i < NPAD; i += nthr) {
        unsigned long long kk = 0ull;
        if (i < NBOX) {
            unsigned cb = __float_as_uint(g_conf[b][i]);
            kk = ((unsigned long long)cb << 32) | (unsigned)(0xFFFFFFFFu - (unsigned)i);
        }
        s_keys[i] = kk;
    }
    __syncthreads();

    for (int k2 = 2; k2 <= NPAD; k2 <<= 1) {
        for (int j = k2 >> 1; j > 0; j >>= 1) {
            for (int i = tid; i < NPAD; i += nthr) {
                int ixj = i ^ j;
                if (ixj > i) {
                    unsigned long long x = s_keys[i];
                    unsigned long long y = s_keys[ixj];
                    bool desc = ((i & k2) == 0);          // overall descending
                    if (desc ? (x < y) : (x > y)) {
                        s_keys[i] = y;
                        s_keys[ixj] = x;
                    }
                }
            }
            __syncthreads();
        }
    }

    for (int i = tid; i < TOPK; i += nthr) {
        unsigned long long kk = s_keys[i];
        int n = (int)(0xFFFFFFFFu - (unsigned)(kk & 0xFFFFFFFFull));
        g_top[b][i] = n;
        out_topidx[b * TOPK + i] = (float)n;
    }
}

// ---------------------------------------------------------------------------
// Kernel 3: greedy class-aware NMS, one CTA per batch.
// Sequential over kept candidates; parallel suppression of j > i.
// All arithmetic rn-intrinsics in the reference's association order.
// ---------------------------------------------------------------------------
__global__ void nms_kernel(const float* __restrict__ out,
                           float* __restrict__ keep_out) {
    __shared__ float sx1[TOPK], sy1[TOPK], sx2[TOPK], sy2[TOPK], sarea[TOPK];
    __shared__ short scls[TOPK];
    __shared__ unsigned char svalid[TOPK];
    __shared__ unsigned int supp[TOPK / 32];
    __shared__ int sel;

    int b = blockIdx.x, tid = threadIdx.x, nthr = blockDim.x;

    for (int i = tid; i < TOPK; i += nthr) {
        int n = g_top[b][i];
        const float* o = out + ((size_t)b * NBOX + n) * NATTR;
        float cx = o[0], cy = o[1], w = o[2], h = o[3], conf = o[4];
        float hw2 = __fmul_rn(w, 0.5f);     // == w/2 (exact)
        float hh2 = __fmul_rn(h, 0.5f);
        float x1 = __fsub_rn(cx, hw2);
        float y1 = __fsub_rn(cy, hh2);
        float x2 = __fadd_rn(cx, hw2);
        float y2 = __fadd_rn(cy, hh2);
        sx1[i] = x1; sy1[i] = y1; sx2[i] = x2; sy2[i] = y2;
        sarea[i] = __fmul_rn(__fadd_rn(__fsub_rn(x2, x1), 1.0f),
                             __fadd_rn(__fsub_rn(y2, y1), 1.0f));
        scls[i]  = (short)g_cls[b][n];
        svalid[i] = (conf >= 0.5f) ? 1 : 0;
    }
    for (int i = tid; i < TOPK / 32; i += nthr) supp[i] = 0u;
    __syncthreads();

    int start = 0;
    while (true) {
        if (tid == 0) {
            int i = start;
            while (i < TOPK) {
                bool s = (supp[i >> 5] >> (i & 31)) & 1u;
                if (svalid[i] && !s) break;
                keep_out[b * TOPK + i] = 0.0f;     // skipped -> keep = 0
                i++;
            }
            if (i < TOPK) keep_out[b * TOPK + i] = 1.0f;  // selected
            sel = i;
        }
        __syncthreads();
        int i = sel;
        if (i >= TOPK) break;

        float xi1 = sx1[i], yi1 = sy1[i], xi2 = sx2[i], yi2 = sy2[i], ai = sarea[i];
        short ci = scls[i];
        for (int j = i + 1 + tid; j < TOPK; j += nthr) {
            if (scls[j] != ci) continue;
            float ix1 = fmaxf(xi1, sx1[j]);
            float iy1 = fmaxf(yi1, sy1[j]);
            float ix2 = fminf(xi2, sx2[j]);
            float iy2 = fminf(yi2, sy2[j]);
            float iw = __fadd_rn(__fsub_rn(ix2, ix1), 1.0f); iw = fmaxf(iw, 0.0f);
            float ih = __fadd_rn(__fsub_rn(iy2, iy1), 1.0f); ih = fmaxf(ih, 0.0f);
            float inter = __fmul_rn(iw, ih);
            float den = __fadd_rn(__fsub_rn(__fadd_rn(ai, sarea[j]), inter), 1e-16f);
            float iou = __fdiv_rn(inter, den);
            if (iou >= 0.4f) atomicOr(&supp[j >> 5], 1u << (j & 31));
        }
        __syncthreads();
        start = i + 1;
    }
}

// ---------------------------------------------------------------------------
// Launch: out = [output(B*NBOX*NATTR) | top_idx(B*TOPK) | keep(B*TOPK)] float32
// ---------------------------------------------------------------------------
extern "C" void kernel_launch(void* const* d_in, const int* in_sizes, int n_in,
                              void* d_out, int out_size) {
    (void)in_sizes; (void)n_in; (void)out_size;
    const float* in      = (const float*)d_in[0];
    const float* anchors = (const float*)d_in[1];
    float* out      = (float*)d_out;
    float* top_out  = out + (size_t)BATCH * NBOX * NATTR;
    float* keep_out = top_out + (size_t)BATCH * TOPK;

    int total = BATCH * NBOX;                 // 129792 = 128 * 1014, no tail
    decode_kernel<<<total / 128, 128>>>(in, anchors, out);

    (void)cudaFuncSetAttribute(sort_kernel,
                               cudaFuncAttributeMaxDynamicSharedMemorySize,
                               NPAD * (int)sizeof(unsigned long long));
    sort_kernel<<<BATCH, 1024, NPAD * sizeof(unsigned long long)>>>(top_out);

    nms_kernel<<<BATCH, 256>>>(out, keep_out);
}

// round 4
// speedup vs baseline: 6.0522x; 6.0522x over previous
#include <cuda_runtime.h>
#include <cstdint>

// Problem constants
#define BATCH 16
#define NA    3
#define NC    20
#define NATTR 25          // 5 + NC
#define IH    52
#define IW    52
#define HW    2704        // IH*IW
#define NBOX  8112        // NA*HW
#define NPAD  8192
#define TOPK  2048
#define NWORDS (TOPK / 64)    // 32 u64 words per suppression row
#define STRIDE_F 8.0f

// Accurate libdevice expf (XLA's f32 exp lowering), immune to --use_fast_math.
extern "C" __device__ float __nv_expf(float);

// Scratch (allocation-free: __device__ globals)
__device__ float g_conf[BATCH][NBOX];
__device__ int   g_cls [BATCH][NBOX];
__device__ int   g_top [BATCH][TOPK];

// NMS staging
__device__ float g_x1[BATCH][TOPK];
__device__ float g_y1[BATCH][TOPK];
__device__ float g_x2[BATCH][TOPK];
__device__ float g_y2[BATCH][TOPK];
__device__ float g_ar[BATCH][TOPK];
__device__ short g_cl[BATCH][TOPK];
__device__ unsigned char g_va[BATCH][TOPK];
__device__ unsigned long long g_mask[BATCH][TOPK][NWORDS];   // 8 MB

// ---------------------------------------------------------------------------
// Bitwise replica of XLA:GPU's tanh (llvm_ir::EmitFastTanh): Eigen ptanh
// rational approximation, fma-contracted Horner, rn division,
// |x| < 4e-4 -> x fast path, clamp to +-7.90531110763549805.
// ---------------------------------------------------------------------------
__device__ __forceinline__ float xla_tanhf(float x) {
    float ax = fabsf(x);
    float xc = fminf(fmaxf(x, -7.90531110763549805f), 7.90531110763549805f);
    float x2 = __fmul_rn(xc, xc);
    float p = -2.76076847742355e-16f;
    p = __fmaf_rn(x2, p, 2.00018790482477e-13f);
    p = __fmaf_rn(x2, p, -8.60467152213735e-11f);
    p = __fmaf_rn(x2, p, 5.12229709037114e-08f);
    p = __fmaf_rn(x2, p, 1.48572235717979e-05f);
    p = __fmaf_rn(x2, p, 6.37261928875436e-04f);
    p = __fmaf_rn(x2, p, 4.89352455891786e-03f);
    p = __fmul_rn(xc, p);
    float q = 1.19825839466702e-06f;
    q = __fmaf_rn(x2, q, 1.18534705686654e-04f);
    q = __fmaf_rn(x2, q, 2.26843463243900e-03f);
    q = __fmaf_rn(x2, q, 4.89352518554385e-03f);
    float r = __fdiv_rn(p, q);
    return (ax < 0.0004f) ? x : r;
}

__device__ __forceinline__ float sigmoid_xla(float x) {
    float t = xla_tanhf(__fmul_rn(0.5f, x));
    return __fmaf_rn(0.5f, t, 0.5f);
}

// ---------------------------------------------------------------------------
// Kernel 1: decode (unchanged from passing round).
// ---------------------------------------------------------------------------
__global__ void decode_kernel(const float* __restrict__ in,
                              const float* __restrict__ anchors,
                              float* __restrict__ out) {
    __shared__ float s_out[128 * NATTR];

    int t = blockIdx.x * 128 + threadIdx.x;     // grid sized exactly: no tail
    int b = t / NBOX, n = t % NBOX;
    int a = n / HW,   r = n % HW;
    int gy = r / IW,  gx = r % IW;

    const float* base = in + ((size_t)(b * NA + a) * NATTR) * HW + r;
    float t0 = base[0 * HW];
    float t1 = base[1 * HW];
    float t2 = base[2 * HW];
    float t3 = base[3 * HW];
    float t4 = base[4 * HW];

    float aw = __fdiv_rn(anchors[a * 2 + 0], STRIDE_F);
    float ah = __fdiv_rn(anchors[a * 2 + 1], STRIDE_F);

    float sx = sigmoid_xla(t0);
    float sy = sigmoid_xla(t1);
    float bx = __fmul_rn(__fadd_rn(sx, (float)gx), STRIDE_F);
    float by = __fmul_rn(__fadd_rn(sy, (float)gy), STRIDE_F);
    float bw = __fmul_rn(__fmul_rn(__nv_expf(t2), aw), STRIDE_F);
    float bh = __fmul_rn(__fmul_rn(__nv_expf(t3), ah), STRIDE_F);
    float conf = sigmoid_xla(t4);

    float* so = s_out + threadIdx.x * NATTR;
    so[0] = bx; so[1] = by; so[2] = bw; so[3] = bh; so[4] = conf;

    float bestv = -3.402823466e+38f;
    int best = 0;
#pragma unroll
    for (int c = 0; c < NC; c++) {
        float v = sigmoid_xla(base[(5 + c) * HW]);
        so[5 + c] = v;
        if (v > bestv) { bestv = v; best = c; }
    }
    g_conf[b][n] = conf;
    g_cls[b][n]  = best;
    __syncthreads();

    float* oblk = out + (size_t)(blockIdx.x) * 128 * NATTR;
    for (int k = threadIdx.x; k < 128 * NATTR; k += 128)
        oblk[k] = s_out[k];
}

// ---------------------------------------------------------------------------
// Kernel 2: per-batch top-K via bitonic sort (unchanged from passing round).
// ---------------------------------------------------------------------------
extern __shared__ unsigned long long s_keys[];

__global__ void sort_kernel(float* __restrict__ out_topidx) {
    int b   = blockIdx.x;
    int tid = threadIdx.x;
    int nthr = blockDim.x;

    for (int i = tid; i < NPAD; i += nthr) {
        unsigned long long kk = 0ull;
        if (i < NBOX) {
            unsigned cb = __float_as_uint(g_conf[b][i]);
            kk = ((unsigned long long)cb << 32) | (unsigned)(0xFFFFFFFFu - (unsigned)i);
        }
        s_keys[i] = kk;
    }
    __syncthreads();

    for (int k2 = 2; k2 <= NPAD; k2 <<= 1) {
        for (int j = k2 >> 1; j > 0; j >>= 1) {
            for (int i = tid; i < NPAD; i += nthr) {
                int ixj = i ^ j;
                if (ixj > i) {
                    unsigned long long x = s_keys[i];
                    unsigned long long y = s_keys[ixj];
                    bool desc = ((i & k2) == 0);
                    if (desc ? (x < y) : (x > y)) {
                        s_keys[i] = y;
                        s_keys[ixj] = x;
                    }
                }
            }
            __syncthreads();
        }
    }

    for (int i = tid; i < TOPK; i += nthr) {
        unsigned long long kk = s_keys[i];
        int n = (int)(0xFFFFFFFFu - (unsigned)(kk & 0xFFFFFFFFull));
        g_top[b][i] = n;
        out_topidx[b * TOPK + i] = (float)n;
    }
}

// ---------------------------------------------------------------------------
// Kernel 3a: prep — corners / area / class / valid per top-K candidate.
// Identical arithmetic to the round-3 NMS prologue (which passed).
// ---------------------------------------------------------------------------
__global__ void nms_prep(const float* __restrict__ out) {
    int b = blockIdx.x;
    for (int i = threadIdx.x; i < TOPK; i += blockDim.x) {
        int n = g_top[b][i];
        const float* o = out + ((size_t)b * NBOX + n) * NATTR;
        float cx = o[0], cy = o[1], w = o[2], h = o[3], conf = o[4];
        float hw2 = __fmul_rn(w, 0.5f);
        float hh2 = __fmul_rn(h, 0.5f);
        float x1 = __fsub_rn(cx, hw2);
        float y1 = __fsub_rn(cy, hh2);
        float x2 = __fadd_rn(cx, hw2);
        float y2 = __fadd_rn(cy, hh2);
        g_x1[b][i] = x1; g_y1[b][i] = y1; g_x2[b][i] = x2; g_y2[b][i] = y2;
        g_ar[b][i] = __fmul_rn(__fadd_rn(__fsub_rn(x2, x1), 1.0f),
                               __fadd_rn(__fsub_rn(y2, y1), 1.0f));
        g_cl[b][i] = (short)g_cls[b][n];
        g_va[b][i] = (conf >= 0.5f) ? 1 : 0;
    }
}

// ---------------------------------------------------------------------------
// Kernel 3b: suppression mask — upper triangle of cond[i][j] packed into u64.
// Block = (jb, ib, b), 64 threads; thread t handles row i = ib*64+t against
// the 64 j's of block jb staged in SMEM. Only jb >= ib blocks do work.
// IoU arithmetic bit-identical to the round-3 kernel.
// ---------------------------------------------------------------------------
__global__ void nms_mask(void) {
    int jb = blockIdx.x, ib = blockIdx.y, b = blockIdx.z;
    if (jb < ib) return;

    __shared__ float jx1[64], jy1[64], jx2[64], jy2[64], jar[64];
    __shared__ short jcl[64];

    int t = threadIdx.x;
    int j0 = jb * 64;
    jx1[t] = g_x1[b][j0 + t];
    jy1[t] = g_y1[b][j0 + t];
    jx2[t] = g_x2[b][j0 + t];
    jy2[t] = g_y2[b][j0 + t];
    jar[t] = g_ar[b][j0 + t];
    jcl[t] = g_cl[b][j0 + t];
    __syncthreads();

    int i = ib * 64 + t;
    float xi1 = g_x1[b][i], yi1 = g_y1[b][i];
    float xi2 = g_x2[b][i], yi2 = g_y2[b][i];
    float ai  = g_ar[b][i];
    short ci  = g_cl[b][i];

    unsigned long long bits = 0ull;
#pragma unroll 4
    for (int jj = 0; jj < 64; jj++) {
        int jg = j0 + jj;
        if (jg > i && jcl[jj] == ci) {
            float ix1 = fmaxf(xi1, jx1[jj]);
            float iy1 = fmaxf(yi1, jy1[jj]);
            float ix2 = fminf(xi2, jx2[jj]);
            float iy2 = fminf(yi2, jy2[jj]);
            float iw = __fadd_rn(__fsub_rn(ix2, ix1), 1.0f); iw = fmaxf(iw, 0.0f);
            float ih = __fadd_rn(__fsub_rn(iy2, iy1), 1.0f); ih = fmaxf(ih, 0.0f);
            float inter = __fmul_rn(iw, ih);
            float den = __fadd_rn(__fsub_rn(__fadd_rn(ai, jar[jj]), inter), 1e-16f);
            float iou = __fdiv_rn(inter, den);
            if (iou >= 0.4f) bits |= 1ull << jj;
        }
    }
    g_mask[b][i][jb] = bits;
}

// ---------------------------------------------------------------------------
// Kernel 3c: greedy reduce — one warp per batch. Lane l owns removed bits
// [64l, 64l+64). Per candidate: owner lane decides keep, shfl-broadcasts,
// all lanes OR in row i. Rows only valid for word >= (i>>6); others skipped.
// ---------------------------------------------------------------------------
__global__ void nms_reduce(float* __restrict__ keep_out) {
    int b = blockIdx.x;
    int lane = threadIdx.x;                     // 32 threads
    unsigned long long removed = 0ull;

    for (int i = 0; i < TOPK; i++) {
        int owner = i >> 6;
        unsigned long long row =
            (lane >= owner) ? g_mask[b][i][lane] : 0ull;
        int ki = 0;
        if (lane == owner)
            ki = (g_va[b][i] && !((removed >> (i & 63)) & 1ull)) ? 1 : 0;
        ki = __shfl_sync(0xFFFFFFFFu, ki, owner);
        if (ki) removed |= row;
        if (lane == owner)
            keep_out[b * TOPK + i] = ki ? 1.0f : 0.0f;
    }
}

// ---------------------------------------------------------------------------
// Launch: out = [output(B*NBOX*NATTR) | top_idx(B*TOPK) | keep(B*TOPK)] float32
// ---------------------------------------------------------------------------
extern "C" void kernel_launch(void* const* d_in, const int* in_sizes, int n_in,
                              void* d_out, int out_size) {
    (void)in_sizes; (void)n_in; (void)out_size;
    const float* in      = (const float*)d_in[0];
    const float* anchors = (const float*)d_in[1];
    float* out      = (float*)d_out;
    float* top_out  = out + (size_t)BATCH * NBOX * NATTR;
    float* keep_out = top_out + (size_t)BATCH * TOPK;

    int total = BATCH * NBOX;                 // 129792 = 128 * 1014, no tail
    decode_kernel<<<total / 128, 128>>>(in, anchors, out);

    (void)cudaFuncSetAttribute(sort_kernel,
                               cudaFuncAttributeMaxDynamicSharedMemorySize,
                               NPAD * (int)sizeof(unsigned long long));
    sort_kernel<<<BATCH, 1024, NPAD * sizeof(unsigned long long)>>>(top_out);

    nms_prep<<<BATCH, 256>>>(out);
    nms_mask<<<dim3(TOPK / 64, TOPK / 64, BATCH), 64>>>();
    nms_reduce<<<BATCH, 32>>>(keep_out);
}

// round 5
// speedup vs baseline: 10.5919x; 1.7501x over previous
#include <cuda_runtime.h>
#include <cstdint>

// Problem constants
#define BATCH 16
#define NA    3
#define NC    20
#define NATTR 25          // 5 + NC
#define IH    52
#define IW    52
#define HW    2704        // IH*IW
#define NBOX  8112        // NA*HW
#define NPAD  8192
#define TOPK  2048
#define NWORDS (TOPK / 64)    // 32 u64 words per suppression row
#define STRIDE_F 8.0f

typedef unsigned long long u64;

// Accurate libdevice expf (XLA's f32 exp lowering), immune to --use_fast_math.
extern "C" __device__ float __nv_expf(float);

// Scratch (allocation-free: __device__ globals)
__device__ float g_conf[BATCH][NBOX];
__device__ int   g_cls [BATCH][NBOX];
__device__ int   g_top [BATCH][TOPK];

// NMS staging
__device__ float g_x1[BATCH][TOPK];
__device__ float g_y1[BATCH][TOPK];
__device__ float g_x2[BATCH][TOPK];
__device__ float g_y2[BATCH][TOPK];
__device__ float g_ar[BATCH][TOPK];
__device__ short g_cl[BATCH][TOPK];
__device__ unsigned char g_va[BATCH][TOPK];
__device__ u64 g_mask[BATCH][TOPK][NWORDS];   // 8 MB

// ---------------------------------------------------------------------------
// Bitwise replica of XLA:GPU's tanh (llvm_ir::EmitFastTanh).
// ---------------------------------------------------------------------------
__device__ __forceinline__ float xla_tanhf(float x) {
    float ax = fabsf(x);
    float xc = fminf(fmaxf(x, -7.90531110763549805f), 7.90531110763549805f);
    float x2 = __fmul_rn(xc, xc);
    float p = -2.76076847742355e-16f;
    p = __fmaf_rn(x2, p, 2.00018790482477e-13f);
    p = __fmaf_rn(x2, p, -8.60467152213735e-11f);
    p = __fmaf_rn(x2, p, 5.12229709037114e-08f);
    p = __fmaf_rn(x2, p, 1.48572235717979e-05f);
    p = __fmaf_rn(x2, p, 6.37261928875436e-04f);
    p = __fmaf_rn(x2, p, 4.89352455891786e-03f);
    p = __fmul_rn(xc, p);
    float q = 1.19825839466702e-06f;
    q = __fmaf_rn(x2, q, 1.18534705686654e-04f);
    q = __fmaf_rn(x2, q, 2.26843463243900e-03f);
    q = __fmaf_rn(x2, q, 4.89352518554385e-03f);
    float r = __fdiv_rn(p, q);
    return (ax < 0.0004f) ? x : r;
}

__device__ __forceinline__ float sigmoid_xla(float x) {
    float t = xla_tanhf(__fmul_rn(0.5f, x));
    return __fmaf_rn(0.5f, t, 0.5f);
}

// ---------------------------------------------------------------------------
// Kernel 1: decode (unchanged — passing & 20us).
// ---------------------------------------------------------------------------
__global__ void decode_kernel(const float* __restrict__ in,
                              const float* __restrict__ anchors,
                              float* __restrict__ out) {
    __shared__ float s_out[128 * NATTR];

    int t = blockIdx.x * 128 + threadIdx.x;     // grid sized exactly: no tail
    int b = t / NBOX, n = t % NBOX;
    int a = n / HW,   r = n % HW;
    int gy = r / IW,  gx = r % IW;

    const float* base = in + ((size_t)(b * NA + a) * NATTR) * HW + r;
    float t0 = base[0 * HW];
    float t1 = base[1 * HW];
    float t2 = base[2 * HW];
    float t3 = base[3 * HW];
    float t4 = base[4 * HW];

    float aw = __fdiv_rn(anchors[a * 2 + 0], STRIDE_F);
    float ah = __fdiv_rn(anchors[a * 2 + 1], STRIDE_F);

    float sx = sigmoid_xla(t0);
    float sy = sigmoid_xla(t1);
    float bx = __fmul_rn(__fadd_rn(sx, (float)gx), STRIDE_F);
    float by = __fmul_rn(__fadd_rn(sy, (float)gy), STRIDE_F);
    float bw = __fmul_rn(__fmul_rn(__nv_expf(t2), aw), STRIDE_F);
    float bh = __fmul_rn(__fmul_rn(__nv_expf(t3), ah), STRIDE_F);
    float conf = sigmoid_xla(t4);

    float* so = s_out + threadIdx.x * NATTR;
    so[0] = bx; so[1] = by; so[2] = bw; so[3] = bh; so[4] = conf;

    float bestv = -3.402823466e+38f;
    int best = 0;
#pragma unroll
    for (int c = 0; c < NC; c++) {
        float v = sigmoid_xla(base[(5 + c) * HW]);
        so[5 + c] = v;
        if (v > bestv) { bestv = v; best = c; }
    }
    g_conf[b][n] = conf;
    g_cls[b][n]  = best;
    __syncthreads();

    float* oblk = out + (size_t)(blockIdx.x) * 128 * NATTR;
    for (int k = threadIdx.x; k < 128 * NATTR; k += 128)
        oblk[k] = s_out[k];
}

// ---------------------------------------------------------------------------
// Kernel 2: per-batch bitonic sort, register-resident (cyclic layout).
// Thread t owns elements i = m*1024 + t, m = 0..7 in registers.
//   j >= 1024 : in-register slot exchange (partner = same thread)
//   32<=j<=512: smem exchange (partner thread t^j, cross-warp)
//   j <= 16   : warp shuffle  (partner lane t^j)
// Same network & comparator as the passing round => identical result.
// ---------------------------------------------------------------------------
extern __shared__ u64 s_keys[];

__device__ __forceinline__ u64 cex(u64 a, u64 v, bool lower, bool desc) {
    u64 mx = a > v ? a : v;
    u64 mn = a > v ? v : a;
    return desc ? (lower ? mx : mn) : (lower ? mn : mx);
}

__global__ void sort_kernel(float* __restrict__ out_topidx) {
    int b = blockIdx.x;
    int t = threadIdx.x;                        // 1024 threads

    u64 r[8];
#pragma unroll
    for (int m = 0; m < 8; m++) {
        int i = m * 1024 + t;
        u64 kk = 0ull;
        if (i < NBOX) {
            unsigned cb = __float_as_uint(g_conf[b][i]);
            kk = ((u64)cb << 32) | (unsigned)(0xFFFFFFFFu - (unsigned)i);
        }
        r[m] = kk;
    }

    for (int k2 = 2; k2 <= NPAD; k2 <<= 1) {
        for (int j = k2 >> 1; j > 0; j >>= 1) {
            if (j >= 1024) {
                int s = j >> 10;                // slot stride 1,2,4
#pragma unroll
                for (int m = 0; m < 8; m++) {
                    if (!(m & s)) {
                        int lo = m, hi = m | s;
                        bool desc = (((lo * 1024 + t) & k2) == 0);
                        u64 a = r[lo], v = r[hi];
                        bool sw = desc ? (a < v) : (a > v);
                        if (sw) { r[lo] = v; r[hi] = a; }
                    }
                }
            } else if (j >= 32) {
#pragma unroll
                for (int m = 0; m < 8; m++) s_keys[m * 1024 + t] = r[m];
                __syncthreads();
#pragma unroll
                for (int m = 0; m < 8; m++) {
                    int i = m * 1024 + t;
                    u64 v = s_keys[i ^ j];
                    bool lower = ((i & j) == 0);
                    bool desc  = ((i & k2) == 0);
                    r[m] = cex(r[m], v, lower, desc);
                }
                __syncthreads();
            } else {
#pragma unroll
                for (int m = 0; m < 8; m++) {
                    int i = m * 1024 + t;
                    u64 v = __shfl_xor_sync(0xFFFFFFFFu, r[m], j);
                    bool lower = ((t & j) == 0);
                    bool desc  = ((i & k2) == 0);
                    r[m] = cex(r[m], v, lower, desc);
                }
            }
        }
    }

    // elements i < TOPK live in slots m = 0,1
#pragma unroll
    for (int m = 0; m < 2; m++) {
        int i = m * 1024 + t;
        u64 kk = r[m];
        int n = (int)(0xFFFFFFFFu - (unsigned)(kk & 0xFFFFFFFFull));
        g_top[b][i] = n;
        out_topidx[b * TOPK + i] = (float)n;
    }
}

// ---------------------------------------------------------------------------
// Kernel 3a: prep — corners / area / class / valid per top-K candidate.
// ---------------------------------------------------------------------------
__global__ void nms_prep(const float* __restrict__ out) {
    int b = blockIdx.x;
    for (int i = threadIdx.x; i < TOPK; i += blockDim.x) {
        int n = g_top[b][i];
        const float* o = out + ((size_t)b * NBOX + n) * NATTR;
        float cx = o[0], cy = o[1], w = o[2], h = o[3], conf = o[4];
        float hw2 = __fmul_rn(w, 0.5f);
        float hh2 = __fmul_rn(h, 0.5f);
        float x1 = __fsub_rn(cx, hw2);
        float y1 = __fsub_rn(cy, hh2);
        float x2 = __fadd_rn(cx, hw2);
        float y2 = __fadd_rn(cy, hh2);
        g_x1[b][i] = x1; g_y1[b][i] = y1; g_x2[b][i] = x2; g_y2[b][i] = y2;
        g_ar[b][i] = __fmul_rn(__fadd_rn(__fsub_rn(x2, x1), 1.0f),
                               __fadd_rn(__fsub_rn(y2, y1), 1.0f));
        g_cl[b][i] = (short)g_cls[b][n];
        g_va[b][i] = (conf >= 0.5f) ? 1 : 0;
    }
}

// ---------------------------------------------------------------------------
// Kernel 3b: suppression mask. Per-class j-bitmasks let each thread visit
// only same-class j's (~3 of 64 on average) instead of scanning all 64.
// IoU arithmetic bit-identical to the passing kernel.
// ---------------------------------------------------------------------------
__global__ void nms_mask(void) {
    int jb = blockIdx.x, ib = blockIdx.y, b = blockIdx.z;
    if (jb < ib) return;

    __shared__ float jx1[64], jy1[64], jx2[64], jy2[64], jar[64];
    __shared__ u64 s_cm[NC];

    int t = threadIdx.x;
    int j0 = jb * 64;
    if (t < NC) s_cm[t] = 0ull;
    __syncthreads();
    jx1[t] = g_x1[b][j0 + t];
    jy1[t] = g_y1[b][j0 + t];
    jx2[t] = g_x2[b][j0 + t];
    jy2[t] = g_y2[b][j0 + t];
    jar[t] = g_ar[b][j0 + t];
    atomicOr(&s_cm[g_cl[b][j0 + t]], 1ull << t);
    __syncthreads();

    int i = ib * 64 + t;
    float xi1 = g_x1[b][i], yi1 = g_y1[b][i];
    float xi2 = g_x2[b][i], yi2 = g_y2[b][i];
    float ai  = g_ar[b][i];
    short ci  = g_cl[b][i];

    u64 mm = s_cm[ci];
    if (jb == ib) mm = (t < 63) ? (mm & (~0ull << (t + 1))) : 0ull;

    u64 bits = 0ull;
    while (mm) {
        int jj = __ffsll((long long)mm) - 1;
        mm &= mm - 1;
        float ix1 = fmaxf(xi1, jx1[jj]);
        float iy1 = fmaxf(yi1, jy1[jj]);
        float ix2 = fminf(xi2, jx2[jj]);
        float iy2 = fminf(yi2, jy2[jj]);
        float iw = __fadd_rn(__fsub_rn(ix2, ix1), 1.0f); iw = fmaxf(iw, 0.0f);
        float ih = __fadd_rn(__fsub_rn(iy2, iy1), 1.0f); ih = fmaxf(ih, 0.0f);
        float inter = __fmul_rn(iw, ih);
        float den = __fadd_rn(__fsub_rn(__fadd_rn(ai, jar[jj]), inter), 1e-16f);
        float iou = __fdiv_rn(inter, den);
        if (iou >= 0.4f) bits |= 1ull << jj;
    }
    g_mask[b][i][jb] = bits;
}

// ---------------------------------------------------------------------------
// Kernel 3c: greedy reduce — one warp per batch, depth-8 row prefetch so the
// L2 latency of g_mask rows is hidden behind 8 shfl-chain iterations.
// ---------------------------------------------------------------------------
__global__ void nms_reduce(float* __restrict__ keep_out) {
    int b = blockIdx.x;
    int lane = threadIdx.x;                     // 32 threads
    u64 removed = 0ull;

    u64 cur[8], nxt[8];
#pragma unroll
    for (int u = 0; u < 8; u++) cur[u] = g_mask[b][u][lane];

    for (int base = 0; base < TOPK; base += 8) {
        if (base + 8 < TOPK) {
#pragma unroll
            for (int u = 0; u < 8; u++) nxt[u] = g_mask[b][base + 8 + u][lane];
        }
#pragma unroll
        for (int u = 0; u < 8; u++) {
            int i = base + u;
            int owner = i >> 6;
            u64 row = (lane >= owner) ? cur[u] : 0ull;
            int ki = 0;
            if (lane == owner)
                ki = (g_va[b][i] && !((removed >> (i & 63)) & 1ull)) ? 1 : 0;
            ki = __shfl_sync(0xFFFFFFFFu, ki, owner);
            if (ki) removed |= row;
            if (lane == owner)
                keep_out[b * TOPK + i] = ki ? 1.0f : 0.0f;
        }
#pragma unroll
        for (int u = 0; u < 8; u++) cur[u] = nxt[u];
    }
}

// ---------------------------------------------------------------------------
// Launch: out = [output(B*NBOX*NATTR) | top_idx(B*TOPK) | keep(B*TOPK)] float32
// ---------------------------------------------------------------------------
extern "C" void kernel_launch(void* const* d_in, const int* in_sizes, int n_in,
                              void* d_out, int out_size) {
    (void)in_sizes; (void)n_in; (void)out_size;
    const float* in      = (const float*)d_in[0];
    const float* anchors = (const float*)d_in[1];
    float* out      = (float*)d_out;
    float* top_out  = out + (size_t)BATCH * NBOX * NATTR;
    float* keep_out = top_out + (size_t)BATCH * TOPK;

    int total = BATCH * NBOX;                 // 129792 = 128 * 1014, no tail
    decode_kernel<<<total / 128, 128>>>(in, anchors, out);

    (void)cudaFuncSetAttribute(sort_kernel,
                               cudaFuncAttributeMaxDynamicSharedMemorySize,
                               NPAD * (int)sizeof(u64));
    sort_kernel<<<BATCH, 1024, NPAD * sizeof(u64)>>>(top_out);

    nms_prep<<<BATCH, 256>>>(out);
    nms_mask<<<dim3(TOPK / 64, TOPK / 64, BATCH), 64>>>();
    nms_reduce<<<BATCH, 32>>>(keep_out);
}